// round 3
// baseline (speedup 1.0000x reference)
#include <cuda_runtime.h>
#include <cuda_bf16.h>
#include <cstdint>
#include <cstddef>

// ============================================================================
// Problem constants
// ============================================================================
#define K_DIM  12288
#define B_ROWS 8192
#define C_ROWS 1000
#define C_PAD  1024

// GEMM tiling: CTA 128x128x64 (s8), 8 warps (4x2), warp tile 32x64
#define BM 128
#define BN 128
#define BK 64
#define NKITER (K_DIM / BK)     // 192
#define STAGES 4
#define ROW_STRIDE 80           // 64B row + 16B pad -> conflict-free LDS
#define A_STAGE_BYTES (BM * ROW_STRIDE)             // 10240
#define B_STAGE_BYTES (BN * ROW_STRIDE)             // 10240
#define STAGE_BYTES (A_STAGE_BYTES + B_STAGE_BYTES) // 20480
#define GEMM_SMEM (STAGES * STAGE_BYTES)            // 81920

// Scratch: sign(X), sign(W) as int8
__device__ int8_t g_Xs[(size_t)B_ROWS * K_DIM];
__device__ int8_t g_Ws[(size_t)C_PAD * K_DIM];

// ============================================================================
// Helpers
// ============================================================================
__device__ __forceinline__ uint32_t smem_u32(const void* p) {
    uint32_t a;
    asm("{ .reg .u64 t; cvta.to.shared.u64 t, %1; cvt.u32.u64 %0, t; }"
        : "=r"(a) : "l"(p));
    return a;
}

__device__ __forceinline__ void cp_async_16(uint32_t smem_dst, const void* gmem_src) {
    asm volatile("cp.async.cg.shared.global [%0], [%1], 16;"
                 :: "r"(smem_dst), "l"(gmem_src) : "memory");
}
__device__ __forceinline__ void cp_async_commit() {
    asm volatile("cp.async.commit_group;" ::: "memory");
}
__device__ __forceinline__ void cp_async_wait2() {
    asm volatile("cp.async.wait_group 2;" ::: "memory");
}
__device__ __forceinline__ void cp_async_wait0() {
    asm volatile("cp.async.wait_group 0;" ::: "memory");
}

// IMMA: D(s32)[16x8] += A(s8)[16x32] * B(s8)[32x8], A row-major, B col-major
__device__ __forceinline__ void mma_s8(int& c0, int& c1, int& c2, int& c3,
                                       int a0, int a1, int a2, int a3,
                                       int b0, int b1) {
    asm volatile(
        "mma.sync.aligned.m16n8k32.row.col.s32.s8.s8.s32 "
        "{%0,%1,%2,%3}, {%4,%5,%6,%7}, {%8,%9}, {%0,%1,%2,%3};"
        : "+r"(c0), "+r"(c1), "+r"(c2), "+r"(c3)
        : "r"(a0), "r"(a1), "r"(a2), "r"(a3), "r"(b0), "r"(b1));
}

// ============================================================================
// Sign-convert kernels (fp32 -> s8 {-1, 0, +1}), 16 elems/thread
// ============================================================================
__device__ __forceinline__ int8_t sgn_s8(float x) {
    return x > 0.f ? (int8_t)1 : (x < 0.f ? (int8_t)-1 : (int8_t)0);
}

__global__ void conv_x_kernel(const float* __restrict__ in) {
    size_t i = ((size_t)blockIdx.x * blockDim.x + threadIdx.x) * 16;
    union { int8_t b[16]; int4 v; } u;
#pragma unroll
    for (int j = 0; j < 4; j++) {
        float4 f = *reinterpret_cast<const float4*>(in + i + j * 4);
        u.b[j * 4 + 0] = sgn_s8(f.x);
        u.b[j * 4 + 1] = sgn_s8(f.y);
        u.b[j * 4 + 2] = sgn_s8(f.z);
        u.b[j * 4 + 3] = sgn_s8(f.w);
    }
    *reinterpret_cast<int4*>(&g_Xs[i]) = u.v;
}

__global__ void conv_w_kernel(const float* __restrict__ in) {
    size_t i = ((size_t)blockIdx.x * blockDim.x + threadIdx.x) * 16;
    union { int8_t b[16]; int4 v; } u;
    if (i < (size_t)C_ROWS * K_DIM) {
#pragma unroll
        for (int j = 0; j < 4; j++) {
            float4 f = *reinterpret_cast<const float4*>(in + i + j * 4);
            u.b[j * 4 + 0] = sgn_s8(f.x);
            u.b[j * 4 + 1] = sgn_s8(f.y);
            u.b[j * 4 + 2] = sgn_s8(f.z);
            u.b[j * 4 + 3] = sgn_s8(f.w);
        }
    } else {
        u.v = make_int4(0, 0, 0, 0);  // pad rows [1000, 1024)
    }
    *reinterpret_cast<int4*>(&g_Ws[i]) = u.v;
}

// ============================================================================
// IMMA GEMM: out[8192,1000] = Xs8[8192,12288] @ Ws8[1024,12288]^T  (s32->f32)
// ============================================================================
__global__ void __launch_bounds__(256, 2) gemm_kernel(float* __restrict__ out) {
    extern __shared__ __align__(16) char sm[];
    const int tid = threadIdx.x;
    const int lane = tid & 31;
    const int warp = tid >> 5;
    const int wm = (warp & 3) * 32;   // warp-m offset (4 warps down M)
    const int wn = (warp >> 2) * 64;  // warp-n offset (2 warps across N)
    const int m0 = blockIdx.x * BM;
    const int n0 = blockIdx.y * BN;
    const uint32_t smem_base = smem_u32(sm);

    // Per-thread load slots: A has 512 16B-chunks, B has 512; 2+2 per thread.
    const int8_t* aSrc[2];
    const int8_t* bSrc[2];
    uint32_t aDst[2], bDst[2];
#pragma unroll
    for (int j = 0; j < 2; j++) {
        int c = tid + j * 256;
        int row = c >> 2, q = c & 3;
        aDst[j] = row * ROW_STRIDE + q * 16;
        bDst[j] = A_STAGE_BYTES + row * ROW_STRIDE + q * 16;
        aSrc[j] = g_Xs + (size_t)(m0 + row) * K_DIM + q * 16;
        bSrc[j] = g_Ws + (size_t)(n0 + row) * K_DIM + q * 16;
    }

    int c[2][8][4];
#pragma unroll
    for (int mt = 0; mt < 2; mt++)
#pragma unroll
        for (int nt = 0; nt < 8; nt++)
#pragma unroll
            for (int r = 0; r < 4; r++) c[mt][nt][r] = 0;

    auto load_stage = [&](int kk, int s) {
        const uint32_t base = smem_base + s * STAGE_BYTES;
        const int koff = kk * BK;
#pragma unroll
        for (int j = 0; j < 2; j++) cp_async_16(base + aDst[j], aSrc[j] + koff);
#pragma unroll
        for (int j = 0; j < 2; j++) cp_async_16(base + bDst[j], bSrc[j] + koff);
        cp_async_commit();
    };

    // Prologue: fill 3 stages
    load_stage(0, 0);
    load_stage(1, 1);
    load_stage(2, 2);

    const char* smc = sm;
    const int qk = (lane & 3) * 4;   // k-byte offset within 16-wide group
    const int r4 = lane >> 2;        // row-in-8 selector

    for (int k = 0; k < NKITER; k++) {
        cp_async_wait2();
        __syncthreads();
        if (k + 3 < NKITER) load_stage(k + 3, (k + 3) & (STAGES - 1));

        const char* As = smc + (k & (STAGES - 1)) * STAGE_BYTES;
        const char* Bs = As + A_STAGE_BYTES;
#pragma unroll
        for (int h = 0; h < 2; h++) {  // two k32 halves of BK=64
            const int kb = h * 32 + qk;
            int a[2][4];
#pragma unroll
            for (int mt = 0; mt < 2; mt++) {
                const char* ap = As + (wm + mt * 16 + r4) * ROW_STRIDE + kb;
                a[mt][0] = *(const int*)(ap);
                a[mt][1] = *(const int*)(ap + 8 * ROW_STRIDE);
                a[mt][2] = *(const int*)(ap + 16);
                a[mt][3] = *(const int*)(ap + 8 * ROW_STRIDE + 16);
            }
            int b[8][2];
#pragma unroll
            for (int nt = 0; nt < 8; nt++) {
                const char* bp = Bs + (wn + nt * 8 + r4) * ROW_STRIDE + kb;
                b[nt][0] = *(const int*)(bp);
                b[nt][1] = *(const int*)(bp + 16);
            }
#pragma unroll
            for (int mt = 0; mt < 2; mt++)
#pragma unroll
                for (int nt = 0; nt < 8; nt++)
                    mma_s8(c[mt][nt][0], c[mt][nt][1], c[mt][nt][2], c[mt][nt][3],
                           a[mt][0], a[mt][1], a[mt][2], a[mt][3],
                           b[nt][0], b[nt][1]);
        }
        __syncthreads();
    }
    cp_async_wait0();

    // Epilogue: s32 -> f32 (exact), clip columns to C_ROWS
#pragma unroll
    for (int mt = 0; mt < 2; mt++) {
        const int row0 = m0 + wm + mt * 16 + r4;
#pragma unroll
        for (int nt = 0; nt < 8; nt++) {
            const int col = n0 + wn + nt * 8 + (lane & 3) * 2;
            if (col < C_ROWS) {
                float2 v0, v1;
                v0.x = (float)c[mt][nt][0];
                v0.y = (float)c[mt][nt][1];
                v1.x = (float)c[mt][nt][2];
                v1.y = (float)c[mt][nt][3];
                *reinterpret_cast<float2*>(out + (size_t)row0 * C_ROWS + col) = v0;
                *reinterpret_cast<float2*>(out + (size_t)(row0 + 8) * C_ROWS + col) = v1;
            }
        }
    }
}

// ============================================================================
// Launch
// ============================================================================
extern "C" void kernel_launch(void* const* d_in, const int* in_sizes, int n_in,
                              void* d_out, int out_size) {
    const float* x = (const float*)d_in[0];  // [8192, 12288] fp32
    const float* w = (const float*)d_in[1];  // [1000, 12288] fp32
    float* out = (float*)d_out;              // [8192, 1000] fp32

    {
        size_t total = (size_t)B_ROWS * K_DIM;   // 100663296
        int blocks = (int)(total / 16 / 256);    // exact: 24576
        conv_x_kernel<<<blocks, 256>>>(x);
    }
    {
        size_t total = (size_t)C_PAD * K_DIM;    // 12582912
        int blocks = (int)(total / 16 / 256);    // exact: 3072
        conv_w_kernel<<<blocks, 256>>>(w);
    }

    static int smem_set = 0;
    if (!smem_set) {
        cudaFuncSetAttribute(gemm_kernel, cudaFuncAttributeMaxDynamicSharedMemorySize,
                             GEMM_SMEM);
        smem_set = 1;
    }
    dim3 grid(B_ROWS / BM, C_PAD / BN);  // (64, 8)
    gemm_kernel<<<grid, 256, GEMM_SMEM>>>(out);
}

// round 4
// speedup vs baseline: 1.9833x; 1.9833x over previous
#include <cuda_runtime.h>
#include <cuda_bf16.h>
#include <cstdint>
#include <cstddef>

// ============================================================================
// Problem constants
// ============================================================================
#define K_DIM  12288
#define KW     (K_DIM / 32)   // 384 packed words per row
#define B_ROWS 8192
#define C_ROWS 1000
#define C_PAD  1024

// GEMM tiling: CTA 128x128, 256 threads, 8x8 outputs/thread
#define BM 128
#define BN 128
#define KC 32                 // k-words per smem chunk
#define NCH (KW / KC)         // 12 chunks
#define A_STAGE_BYTES (KC * BM * 4)   // 16384
#define B_STAGE_BYTES (KC * BN * 4)   // 16384
#define STAGE_BYTES (A_STAGE_BYTES + B_STAGE_BYTES)
#define GEMM_SMEM (2 * STAGE_BYTES)   // 65536

// Packed sign bits, k-major: g_Xp[kw][m], g_Wp[kw][n]  (bit=1 <=> value < 0)
__device__ uint32_t g_Xp[(size_t)KW * B_ROWS];   // 12.6 MB
__device__ uint32_t g_Wp[(size_t)KW * C_PAD];    //  1.6 MB

// ============================================================================
// Helpers
// ============================================================================
__device__ __forceinline__ uint32_t smem_u32(const void* p) {
    uint32_t a;
    asm("{ .reg .u64 t; cvta.to.shared.u64 t, %1; cvt.u32.u64 %0, t; }"
        : "=r"(a) : "l"(p));
    return a;
}
__device__ __forceinline__ void cp_async_16(uint32_t smem_dst, const void* gmem_src) {
    asm volatile("cp.async.cg.shared.global [%0], [%1], 16;"
                 :: "r"(smem_dst), "l"(gmem_src) : "memory");
}
__device__ __forceinline__ void cp_async_commit() {
    asm volatile("cp.async.commit_group;" ::: "memory");
}
__device__ __forceinline__ void cp_async_wait1() {
    asm volatile("cp.async.wait_group 1;" ::: "memory");
}
__device__ __forceinline__ void cp_async_wait0() {
    asm volatile("cp.async.wait_group 0;" ::: "memory");
}

// ============================================================================
// Pack kernels: fp32 -> sign bits, k-major layout.
// Thread handles one packed word = 32 consecutive floats of one row
// (one full 128B line per lane); writes are fully coalesced across threads.
// ============================================================================
__global__ void pack_x_kernel(const float* __restrict__ in) {
    const int m = blockIdx.x * 256 + threadIdx.x;     // 0..8191
    const int kw = blockIdx.y;                        // 0..383
    const float4* p = reinterpret_cast<const float4*>(in + (size_t)m * K_DIM + kw * 32);
    uint32_t w = 0;
#pragma unroll
    for (int j = 0; j < 8; j++) {
        float4 f = p[j];
        w |= (__float_as_uint(f.x) >> 31) << (4 * j + 0);
        w |= (__float_as_uint(f.y) >> 31) << (4 * j + 1);
        w |= (__float_as_uint(f.z) >> 31) << (4 * j + 2);
        w |= (__float_as_uint(f.w) >> 31) << (4 * j + 3);
    }
    g_Xp[(size_t)kw * B_ROWS + m] = w;
}

__global__ void pack_w_kernel(const float* __restrict__ in) {
    const int n = blockIdx.x * 256 + threadIdx.x;     // 0..1023
    const int kw = blockIdx.y;                        // 0..383
    uint32_t w = 0;
    if (n < C_ROWS) {
        const float4* p = reinterpret_cast<const float4*>(in + (size_t)n * K_DIM + kw * 32);
#pragma unroll
        for (int j = 0; j < 8; j++) {
            float4 f = p[j];
            w |= (__float_as_uint(f.x) >> 31) << (4 * j + 0);
            w |= (__float_as_uint(f.y) >> 31) << (4 * j + 1);
            w |= (__float_as_uint(f.z) >> 31) << (4 * j + 2);
            w |= (__float_as_uint(f.w) >> 31) << (4 * j + 3);
        }
    }
    g_Wp[(size_t)kw * C_PAD + n] = w;
}

// ============================================================================
// Binary GEMM: out[m][n] = K - 2*popc(X[m] ^ W[n]) over 384 words.
// CTA 128x128, double-buffered cp.async, 8x8 register tile per thread.
// ============================================================================
__global__ void __launch_bounds__(256, 2) bgemm_kernel(float* __restrict__ out) {
    extern __shared__ __align__(16) uint32_t sm[];
    const int tid = threadIdx.x;
    const int ty = tid >> 4;          // 0..15 -> m sub-tile
    const int tx = tid & 15;          // 0..15 -> n sub-tile
    const int m0 = blockIdx.x * BM;
    const int n0 = blockIdx.y * BN;
    const uint32_t smem_base = smem_u32(sm);

    // cp.async slots: A chunk = KC*BM words = 1024 x 16B chunks; 4/thread. Same for B.
    uint32_t aDst[4], bDst[4];
    const uint32_t* aSrc[4];
    const uint32_t* bSrc[4];
#pragma unroll
    for (int j = 0; j < 4; j++) {
        int c = tid + j * 256;
        int row = c >> 5, c16 = c & 31;            // row: k-word in chunk, c16: 16B chunk
        aDst[j] = row * (BM * 4) + c16 * 16;
        bDst[j] = A_STAGE_BYTES + row * (BN * 4) + c16 * 16;
        aSrc[j] = g_Xp + (size_t)row * B_ROWS + m0 + c16 * 4;
        bSrc[j] = g_Wp + (size_t)row * C_PAD + n0 + c16 * 4;
    }

    auto load_stage = [&](int ch, int s) {
        const uint32_t base = smem_base + s * STAGE_BYTES;
        const size_t koffA = (size_t)ch * KC * B_ROWS;
        const size_t koffB = (size_t)ch * KC * C_PAD;
#pragma unroll
        for (int j = 0; j < 4; j++) cp_async_16(base + aDst[j], aSrc[j] + koffA);
#pragma unroll
        for (int j = 0; j < 4; j++) cp_async_16(base + bDst[j], bSrc[j] + koffB);
        cp_async_commit();
    };

    int acc[8][8];
#pragma unroll
    for (int i = 0; i < 8; i++)
#pragma unroll
        for (int j = 0; j < 8; j++) acc[i][j] = 0;

    load_stage(0, 0);

    for (int ch = 0; ch < NCH; ch++) {
        if (ch + 1 < NCH) {
            load_stage(ch + 1, (ch + 1) & 1);
            cp_async_wait1();
        } else {
            cp_async_wait0();
        }
        __syncthreads();

        const uint32_t* As = sm + (ch & 1) * (STAGE_BYTES / 4);
        const uint32_t* Bs = As + (A_STAGE_BYTES / 4);
        const uint32_t* ap = As + ty * 8;
        const uint32_t* bp = Bs + tx * 8;

#pragma unroll 2
        for (int kw = 0; kw < KC; kw++) {
            uint4 a0 = *reinterpret_cast<const uint4*>(ap + kw * BM);
            uint4 a1 = *reinterpret_cast<const uint4*>(ap + kw * BM + 4);
            uint4 b0 = *reinterpret_cast<const uint4*>(bp + kw * BN);
            uint4 b1 = *reinterpret_cast<const uint4*>(bp + kw * BN + 4);
            uint32_t a[8] = {a0.x, a0.y, a0.z, a0.w, a1.x, a1.y, a1.z, a1.w};
            uint32_t b[8] = {b0.x, b0.y, b0.z, b0.w, b1.x, b1.y, b1.z, b1.w};
#pragma unroll
            for (int i = 0; i < 8; i++)
#pragma unroll
                for (int j = 0; j < 8; j++)
                    acc[i][j] += __popc(a[i] ^ b[j]);
        }
        __syncthreads();
    }

    // Epilogue: dot = K - 2*diff, exact in fp32. Clip columns to C_ROWS.
    const int colBase = n0 + tx * 8;
    const bool full = (colBase + 7 < C_ROWS);
#pragma unroll
    for (int i = 0; i < 8; i++) {
        float* orow = out + (size_t)(m0 + ty * 8 + i) * C_ROWS + colBase;
        float v[8];
#pragma unroll
        for (int j = 0; j < 8; j++) v[j] = (float)(K_DIM - 2 * acc[i][j]);
        if (full) {
            *reinterpret_cast<float4*>(orow) = make_float4(v[0], v[1], v[2], v[3]);
            *reinterpret_cast<float4*>(orow + 4) = make_float4(v[4], v[5], v[6], v[7]);
        } else {
#pragma unroll
            for (int j = 0; j < 8; j++)
                if (colBase + j < C_ROWS) orow[j] = v[j];
        }
    }
}

// ============================================================================
// Launch
// ============================================================================
extern "C" void kernel_launch(void* const* d_in, const int* in_sizes, int n_in,
                              void* d_out, int out_size) {
    const float* x = (const float*)d_in[0];  // [8192, 12288] fp32
    const float* w = (const float*)d_in[1];  // [1000, 12288] fp32
    float* out = (float*)d_out;              // [8192, 1000] fp32

    {
        dim3 g(B_ROWS / 256, KW);            // (32, 384)
        pack_x_kernel<<<g, 256>>>(x);
    }
    {
        dim3 g(C_PAD / 256, KW);             // (4, 384)
        pack_w_kernel<<<g, 256>>>(w);
    }

    static int smem_set = 0;
    if (!smem_set) {
        cudaFuncSetAttribute(bgemm_kernel, cudaFuncAttributeMaxDynamicSharedMemorySize,
                             GEMM_SMEM);
        smem_set = 1;
    }
    dim3 grid(B_ROWS / BM, C_PAD / BN);      // (64, 8)
    bgemm_kernel<<<grid, 256, GEMM_SMEM>>>(out);
}

// round 8
// speedup vs baseline: 1.9920x; 1.0044x over previous
#include <cuda_runtime.h>
#include <cuda_bf16.h>
#include <cstdint>
#include <cstddef>

// ============================================================================
// Problem constants
// ============================================================================
#define K_DIM  12288
#define KW     (K_DIM / 32)   // 384 packed words per row
#define B_ROWS 8192
#define C_ROWS 1000
#define C_PAD  1024

// GEMM tiling: CTA 128x128, 256 threads, 8x8 outputs/thread
#define BM 128
#define BN 128
#define KC 32                 // k-words per smem chunk
#define NCH (KW / KC)         // 12 chunks
#define A_STAGE_BYTES (KC * BM * 4)   // 16384
#define B_STAGE_BYTES (KC * BN * 4)   // 16384
#define STAGE_BYTES (A_STAGE_BYTES + B_STAGE_BYTES)
#define GEMM_SMEM (2 * STAGE_BYTES)   // 65536

// Packed sign bits, k-major: g_Xp[kw][m], g_Wp[kw][n]  (bit=1 <=> value < 0)
__device__ uint32_t g_Xp[(size_t)KW * B_ROWS];   // 12.6 MB
__device__ uint32_t g_Wp[(size_t)KW * C_PAD];    //  1.6 MB

// ============================================================================
// Helpers
// ============================================================================
__device__ __forceinline__ uint32_t smem_u32(const void* p) {
    uint32_t a;
    asm("{ .reg .u64 t; cvta.to.shared.u64 t, %1; cvt.u32.u64 %0, t; }"
        : "=r"(a) : "l"(p));
    return a;
}
__device__ __forceinline__ void cp_async_16(uint32_t smem_dst, const void* gmem_src) {
    asm volatile("cp.async.cg.shared.global [%0], [%1], 16;"
                 :: "r"(smem_dst), "l"(gmem_src) : "memory");
}
__device__ __forceinline__ void cp_async_commit() {
    asm volatile("cp.async.commit_group;" ::: "memory");
}
__device__ __forceinline__ void cp_async_wait1() {
    asm volatile("cp.async.wait_group 1;" ::: "memory");
}
__device__ __forceinline__ void cp_async_wait0() {
    asm volatile("cp.async.wait_group 0;" ::: "memory");
}
__device__ __forceinline__ float4 ldcs4(const float4* p) {
    float4 v;
    asm volatile("ld.global.cs.v4.f32 {%0,%1,%2,%3}, [%4];"
                 : "=f"(v.x), "=f"(v.y), "=f"(v.z), "=f"(v.w) : "l"(p));
    return v;
}
__device__ __forceinline__ void stcs(uint32_t* p, uint32_t v) {
    asm volatile("st.global.cs.u32 [%0], %1;" :: "l"(p), "r"(v));
}

// ============================================================================
// Pack kernels: fp32 -> sign bits, k-major layout. Streaming loads (no L1
// allocation) since each line is touched exactly once.
// ============================================================================
__global__ void pack_x_kernel(const float* __restrict__ in) {
    const int m = blockIdx.x * 256 + threadIdx.x;     // 0..8191
    const int kw = blockIdx.y;                        // 0..383
    const float4* p = reinterpret_cast<const float4*>(in + (size_t)m * K_DIM + kw * 32);
    uint32_t w = 0;
#pragma unroll
    for (int j = 0; j < 8; j++) {
        float4 f = ldcs4(p + j);
        w |= (__float_as_uint(f.x) >> 31) << (4 * j + 0);
        w |= (__float_as_uint(f.y) >> 31) << (4 * j + 1);
        w |= (__float_as_uint(f.z) >> 31) << (4 * j + 2);
        w |= (__float_as_uint(f.w) >> 31) << (4 * j + 3);
    }
    stcs(&g_Xp[(size_t)kw * B_ROWS + m], w);
}

__global__ void pack_w_kernel(const float* __restrict__ in) {
    const int n = blockIdx.x * 256 + threadIdx.x;     // 0..1023
    const int kw = blockIdx.y;                        // 0..383
    uint32_t w = 0;
    if (n < C_ROWS) {
        const float4* p = reinterpret_cast<const float4*>(in + (size_t)n * K_DIM + kw * 32);
#pragma unroll
        for (int j = 0; j < 8; j++) {
            float4 f = ldcs4(p + j);
            w |= (__float_as_uint(f.x) >> 31) << (4 * j + 0);
            w |= (__float_as_uint(f.y) >> 31) << (4 * j + 1);
            w |= (__float_as_uint(f.z) >> 31) << (4 * j + 2);
            w |= (__float_as_uint(f.w) >> 31) << (4 * j + 3);
        }
    }
    stcs(&g_Wp[(size_t)kw * C_PAD + n], w);
}

// ============================================================================
// Binary GEMM: out[m][n] = K - 2*popc(X[m] ^ W[n]) over 384 words.
// CTA 128x128, double-buffered cp.async, 8x8 register tile per thread,
// k-words processed in PAIRS so each accumulate is a single IADD3.
// ============================================================================
__global__ void __launch_bounds__(256, 2) bgemm_kernel(float* __restrict__ out) {
    extern __shared__ __align__(16) uint32_t sm[];
    const int tid = threadIdx.x;
    const int ty = tid >> 4;          // 0..15 -> m sub-tile
    const int tx = tid & 15;          // 0..15 -> n sub-tile
    const int m0 = blockIdx.x * BM;
    const int n0 = blockIdx.y * BN;
    const uint32_t smem_base = smem_u32(sm);

    // cp.async slots: A chunk = KC*BM words = 1024 x 16B chunks; 4/thread. Same for B.
    uint32_t aDst[4], bDst[4];
    const uint32_t* aSrc[4];
    const uint32_t* bSrc[4];
#pragma unroll
    for (int j = 0; j < 4; j++) {
        int c = tid + j * 256;
        int row = c >> 5, c16 = c & 31;            // row: k-word in chunk, c16: 16B chunk
        aDst[j] = row * (BM * 4) + c16 * 16;
        bDst[j] = A_STAGE_BYTES + row * (BN * 4) + c16 * 16;
        aSrc[j] = g_Xp + (size_t)row * B_ROWS + m0 + c16 * 4;
        bSrc[j] = g_Wp + (size_t)row * C_PAD + n0 + c16 * 4;
    }

    auto load_stage = [&](int ch, int s) {
        const uint32_t base = smem_base + s * STAGE_BYTES;
        const size_t koffA = (size_t)ch * KC * B_ROWS;
        const size_t koffB = (size_t)ch * KC * C_PAD;
#pragma unroll
        for (int j = 0; j < 4; j++) cp_async_16(base + aDst[j], aSrc[j] + koffA);
#pragma unroll
        for (int j = 0; j < 4; j++) cp_async_16(base + bDst[j], bSrc[j] + koffB);
        cp_async_commit();
    };

    int acc[8][8];
#pragma unroll
    for (int i = 0; i < 8; i++)
#pragma unroll
        for (int j = 0; j < 8; j++) acc[i][j] = 0;

    load_stage(0, 0);

    for (int ch = 0; ch < NCH; ch++) {
        if (ch + 1 < NCH) {
            load_stage(ch + 1, (ch + 1) & 1);
            cp_async_wait1();
        } else {
            cp_async_wait0();
        }
        __syncthreads();

        const uint32_t* As = sm + (ch & 1) * (STAGE_BYTES / 4);
        const uint32_t* Bs = As + (A_STAGE_BYTES / 4);
        const uint32_t* ap = As + ty * 8;
        const uint32_t* bp = Bs + tx * 8;

#pragma unroll 2
        for (int kw = 0; kw < KC; kw += 2) {
            // k-word pair: load both words' fragments
            uint4 a00 = *reinterpret_cast<const uint4*>(ap + kw * BM);
            uint4 a01 = *reinterpret_cast<const uint4*>(ap + kw * BM + 4);
            uint4 a10 = *reinterpret_cast<const uint4*>(ap + (kw + 1) * BM);
            uint4 a11 = *reinterpret_cast<const uint4*>(ap + (kw + 1) * BM + 4);
            uint4 b00 = *reinterpret_cast<const uint4*>(bp + kw * BN);
            uint4 b01 = *reinterpret_cast<const uint4*>(bp + kw * BN + 4);
            uint4 b10 = *reinterpret_cast<const uint4*>(bp + (kw + 1) * BN);
            uint4 b11 = *reinterpret_cast<const uint4*>(bp + (kw + 1) * BN + 4);
            uint32_t a0[8] = {a00.x, a00.y, a00.z, a00.w, a01.x, a01.y, a01.z, a01.w};
            uint32_t a1[8] = {a10.x, a10.y, a10.z, a10.w, a11.x, a11.y, a11.z, a11.w};
            uint32_t b0[8] = {b00.x, b00.y, b00.z, b00.w, b01.x, b01.y, b01.z, b01.w};
            uint32_t b1[8] = {b10.x, b10.y, b10.z, b10.w, b11.x, b11.y, b11.z, b11.w};
#pragma unroll
            for (int i = 0; i < 8; i++)
#pragma unroll
                for (int j = 0; j < 8; j++)
                    acc[i][j] += __popc(a0[i] ^ b0[j]) + __popc(a1[i] ^ b1[j]);
        }
        __syncthreads();
    }

    // Epilogue: dot = K - 2*diff, exact in fp32. Clip columns to C_ROWS.
    const int colBase = n0 + tx * 8;
    const bool full = (colBase + 7 < C_ROWS);
#pragma unroll
    for (int i = 0; i < 8; i++) {
        float* orow = out + (size_t)(m0 + ty * 8 + i) * C_ROWS + colBase;
        float v[8];
#pragma unroll
        for (int j = 0; j < 8; j++) v[j] = (float)(K_DIM - 2 * acc[i][j]);
        if (full) {
            *reinterpret_cast<float4*>(orow) = make_float4(v[0], v[1], v[2], v[3]);
            *reinterpret_cast<float4*>(orow + 4) = make_float4(v[4], v[5], v[6], v[7]);
        } else {
#pragma unroll
            for (int j = 0; j < 8; j++)
                if (colBase + j < C_ROWS) orow[j] = v[j];
        }
    }
}

// ============================================================================
// Launch
// ============================================================================
extern "C" void kernel_launch(void* const* d_in, const int* in_sizes, int n_in,
                              void* d_out, int out_size) {
    const float* x = (const float*)d_in[0];  // [8192, 12288] fp32
    const float* w = (const float*)d_in[1];  // [1000, 12288] fp32
    float* out = (float*)d_out;              // [8192, 1000] fp32

    {
        dim3 g(B_ROWS / 256, KW);            // (32, 384)
        pack_x_kernel<<<g, 256>>>(x);
    }
    {
        dim3 g(C_PAD / 256, KW);             // (4, 384)
        pack_w_kernel<<<g, 256>>>(w);
    }

    static int smem_set = 0;
    if (!smem_set) {
        cudaFuncSetAttribute(bgemm_kernel, cudaFuncAttributeMaxDynamicSharedMemorySize,
                             GEMM_SMEM);
        smem_set = 1;
    }
    dim3 grid(B_ROWS / BM, C_PAD / BN);      // (64, 8)
    bgemm_kernel<<<grid, 256, GEMM_SMEM>>>(out);
}

// round 9
// speedup vs baseline: 2.3268x; 1.1681x over previous
#include <cuda_runtime.h>
#include <cuda_bf16.h>
#include <cstdint>
#include <cstddef>

// ============================================================================
// Problem constants
// ============================================================================
#define K_DIM  12288
#define KW     (K_DIM / 32)   // 384 packed words per row
#define B_ROWS 8192
#define C_ROWS 1000
#define C_PAD  1024

// GEMM tiling: CTA 128x128, 256 threads, 8x8 outputs/thread
#define BM 128
#define BN 128
#define KC 48                 // k-words per smem chunk (divisible by 3)
#define NCH (KW / KC)         // 8 chunks
#define A_STAGE_BYTES (KC * BM * 4)   // 24576
#define B_STAGE_BYTES (KC * BN * 4)   // 24576
#define STAGE_BYTES (A_STAGE_BYTES + B_STAGE_BYTES)  // 49152
#define GEMM_SMEM (2 * STAGE_BYTES)   // 98304

// Packed sign bits, k-major: g_Xp[kw][m], g_Wp[kw][n]  (bit=1 <=> value < 0)
__device__ uint32_t g_Xp[(size_t)KW * B_ROWS];   // 12.6 MB
__device__ uint32_t g_Wp[(size_t)KW * C_PAD];    //  1.6 MB

// ============================================================================
// Helpers
// ============================================================================
__device__ __forceinline__ uint32_t smem_u32(const void* p) {
    uint32_t a;
    asm("{ .reg .u64 t; cvta.to.shared.u64 t, %1; cvt.u32.u64 %0, t; }"
        : "=r"(a) : "l"(p));
    return a;
}
__device__ __forceinline__ void cp_async_16(uint32_t smem_dst, const void* gmem_src) {
    asm volatile("cp.async.cg.shared.global [%0], [%1], 16;"
                 :: "r"(smem_dst), "l"(gmem_src) : "memory");
}
__device__ __forceinline__ void cp_async_commit() {
    asm volatile("cp.async.commit_group;" ::: "memory");
}
__device__ __forceinline__ void cp_async_wait1() {
    asm volatile("cp.async.wait_group 1;" ::: "memory");
}
__device__ __forceinline__ void cp_async_wait0() {
    asm volatile("cp.async.wait_group 0;" ::: "memory");
}
// Carry-save adder primitives: one LOP3 each.
__device__ __forceinline__ uint32_t xor3(uint32_t a, uint32_t b, uint32_t c) {
    uint32_t r;
    asm("lop3.b32 %0, %1, %2, %3, 0x96;" : "=r"(r) : "r"(a), "r"(b), "r"(c));
    return r;
}
__device__ __forceinline__ uint32_t maj3(uint32_t a, uint32_t b, uint32_t c) {
    uint32_t r;
    asm("lop3.b32 %0, %1, %2, %3, 0xE8;" : "=r"(r) : "r"(a), "r"(b), "r"(c));
    return r;
}

// ============================================================================
// Pack kernels: warp-ballot packing. Lane l reads float base+l (one 128B line
// per warp-op, fully coalesced); ballot of sign bits IS the packed word.
// Each warp owns one row, looping over 48 consecutive k-words.
// ============================================================================
__global__ void pack_x_kernel(const float* __restrict__ in) {
    const int warp = threadIdx.x >> 5;
    const int lane = threadIdx.x & 31;
    const int m = blockIdx.x * 8 + warp;          // grid.x = 1024
    const int kw0 = blockIdx.y * 48;              // grid.y = 8
    const float* p = in + (size_t)m * K_DIM + kw0 * 32 + lane;
#pragma unroll 4
    for (int t = 0; t < 48; t++) {
        float f = __ldcs(p + t * 32);
        unsigned w = __ballot_sync(0xFFFFFFFFu, (__float_as_uint(f) >> 31) != 0u);
        if (lane == 0) g_Xp[(size_t)(kw0 + t) * B_ROWS + m] = w;
    }
}

__global__ void pack_w_kernel(const float* __restrict__ in) {
    const int warp = threadIdx.x >> 5;
    const int lane = threadIdx.x & 31;
    const int n = blockIdx.x * 8 + warp;          // grid.x = 128 -> 0..1023
    const int kw0 = blockIdx.y * 48;
    if (n < C_ROWS) {
        const float* p = in + (size_t)n * K_DIM + kw0 * 32 + lane;
#pragma unroll 4
        for (int t = 0; t < 48; t++) {
            float f = __ldcs(p + t * 32);
            unsigned w = __ballot_sync(0xFFFFFFFFu, (__float_as_uint(f) >> 31) != 0u);
            if (lane == 0) g_Wp[(size_t)(kw0 + t) * C_PAD + n] = w;
        }
    } else {
        if (lane == 0) {
            for (int t = 0; t < 48; t++)
                g_Wp[(size_t)(kw0 + t) * C_PAD + n] = 0u;  // pad rows -> +1s, clipped anyway
        }
    }
}

// ============================================================================
// Binary GEMM with 3:2 carry-save compression:
//   per 3 xor-words: popc(x0)+popc(x1)+popc(x2) = popc(s) + 2*popc(c)
// CTA 128x128, double-buffered cp.async, 8x8 register tile per thread.
// ============================================================================
__global__ void __launch_bounds__(256, 2) bgemm_kernel(float* __restrict__ out) {
    extern __shared__ __align__(16) uint32_t sm[];
    const int tid = threadIdx.x;
    const int ty = tid >> 4;          // 0..15 -> m sub-tile
    const int tx = tid & 15;          // 0..15 -> n sub-tile
    const int m0 = blockIdx.x * BM;
    const int n0 = blockIdx.y * BN;
    const uint32_t smem_base = smem_u32(sm);

    // cp.async slots: A chunk = KC*BM words = 1536 x 16B chunks; 6/thread. Same for B.
    uint32_t aDst[6], bDst[6];
    const uint32_t* aSrc[6];
    const uint32_t* bSrc[6];
#pragma unroll
    for (int j = 0; j < 6; j++) {
        int c = tid + j * 256;
        int row = c >> 5, c32 = c & 31;            // row: k-word in chunk, c32: 16B chunk
        aDst[j] = row * (BM * 4) + c32 * 16;
        bDst[j] = A_STAGE_BYTES + row * (BN * 4) + c32 * 16;
        aSrc[j] = g_Xp + (size_t)row * B_ROWS + m0 + c32 * 4;
        bSrc[j] = g_Wp + (size_t)row * C_PAD + n0 + c32 * 4;
    }

    auto load_stage = [&](int ch, int s) {
        const uint32_t base = smem_base + s * STAGE_BYTES;
        const size_t koffA = (size_t)ch * KC * B_ROWS;
        const size_t koffB = (size_t)ch * KC * C_PAD;
#pragma unroll
        for (int j = 0; j < 6; j++) cp_async_16(base + aDst[j], aSrc[j] + koffA);
#pragma unroll
        for (int j = 0; j < 6; j++) cp_async_16(base + bDst[j], bSrc[j] + koffB);
        cp_async_commit();
    };

    int acc[8][8];
#pragma unroll
    for (int i = 0; i < 8; i++)
#pragma unroll
        for (int j = 0; j < 8; j++) acc[i][j] = 0;

    load_stage(0, 0);

    for (int ch = 0; ch < NCH; ch++) {
        if (ch + 1 < NCH) {
            load_stage(ch + 1, (ch + 1) & 1);
            cp_async_wait1();
        } else {
            cp_async_wait0();
        }
        __syncthreads();

        const uint32_t* As = sm + (ch & 1) * (STAGE_BYTES / 4);
        const uint32_t* Bs = As + (A_STAGE_BYTES / 4);
        const uint32_t* ap = As + ty * 8;
        const uint32_t* bp = Bs + tx * 8;

#pragma unroll 2
        for (int g = 0; g < KC / 3; g++) {
            const int kw = g * 3;
            // A fragments: 3 words x 8 m-rows (6 uint4 loads)
            uint32_t A0[8], A1[8], A2[8];
            {
                uint4 l0 = *reinterpret_cast<const uint4*>(ap + (kw + 0) * BM);
                uint4 h0 = *reinterpret_cast<const uint4*>(ap + (kw + 0) * BM + 4);
                uint4 l1 = *reinterpret_cast<const uint4*>(ap + (kw + 1) * BM);
                uint4 h1 = *reinterpret_cast<const uint4*>(ap + (kw + 1) * BM + 4);
                uint4 l2 = *reinterpret_cast<const uint4*>(ap + (kw + 2) * BM);
                uint4 h2 = *reinterpret_cast<const uint4*>(ap + (kw + 2) * BM + 4);
                A0[0]=l0.x; A0[1]=l0.y; A0[2]=l0.z; A0[3]=l0.w;
                A0[4]=h0.x; A0[5]=h0.y; A0[6]=h0.z; A0[7]=h0.w;
                A1[0]=l1.x; A1[1]=l1.y; A1[2]=l1.z; A1[3]=l1.w;
                A1[4]=h1.x; A1[5]=h1.y; A1[6]=h1.z; A1[7]=h1.w;
                A2[0]=l2.x; A2[1]=l2.y; A2[2]=l2.z; A2[3]=l2.w;
                A2[4]=h2.x; A2[5]=h2.y; A2[6]=h2.z; A2[7]=h2.w;
            }
            // B in two halves of 4 n-words to bound register pressure
#pragma unroll
            for (int half = 0; half < 2; half++) {
                uint4 b0 = *reinterpret_cast<const uint4*>(bp + (kw + 0) * BN + half * 4);
                uint4 b1 = *reinterpret_cast<const uint4*>(bp + (kw + 1) * BN + half * 4);
                uint4 b2 = *reinterpret_cast<const uint4*>(bp + (kw + 2) * BN + half * 4);
                uint32_t B0[4] = {b0.x, b0.y, b0.z, b0.w};
                uint32_t B1[4] = {b1.x, b1.y, b1.z, b1.w};
                uint32_t B2[4] = {b2.x, b2.y, b2.z, b2.w};
#pragma unroll
                for (int i = 0; i < 8; i++)
#pragma unroll
                    for (int j = 0; j < 4; j++) {
                        uint32_t x0 = A0[i] ^ B0[j];
                        uint32_t x1 = A1[i] ^ B1[j];
                        uint32_t x2 = A2[i] ^ B2[j];
                        uint32_t s = xor3(x0, x1, x2);
                        uint32_t c = maj3(x0, x1, x2);
                        acc[i][half * 4 + j] += __popc(s) + 2 * __popc(c);
                    }
            }
        }
        __syncthreads();
    }

    // Epilogue: dot = K - 2*mismatch, exact in fp32. Clip columns to C_ROWS.
    const int colBase = n0 + tx * 8;
    const bool full = (colBase + 7 < C_ROWS);
#pragma unroll
    for (int i = 0; i < 8; i++) {
        float* orow = out + (size_t)(m0 + ty * 8 + i) * C_ROWS + colBase;
        float v[8];
#pragma unroll
        for (int j = 0; j < 8; j++) v[j] = (float)(K_DIM - 2 * acc[i][j]);
        if (full) {
            *reinterpret_cast<float4*>(orow) = make_float4(v[0], v[1], v[2], v[3]);
            *reinterpret_cast<float4*>(orow + 4) = make_float4(v[4], v[5], v[6], v[7]);
        } else {
#pragma unroll
            for (int j = 0; j < 8; j++)
                if (colBase + j < C_ROWS) orow[j] = v[j];
        }
    }
}

// ============================================================================
// Launch
// ============================================================================
extern "C" void kernel_launch(void* const* d_in, const int* in_sizes, int n_in,
                              void* d_out, int out_size) {
    const float* x = (const float*)d_in[0];  // [8192, 12288] fp32
    const float* w = (const float*)d_in[1];  // [1000, 12288] fp32
    float* out = (float*)d_out;              // [8192, 1000] fp32

    {
        dim3 g(B_ROWS / 8, 8);               // (1024, 8)
        pack_x_kernel<<<g, 256>>>(x);
    }
    {
        dim3 g(C_PAD / 8, 8);                // (128, 8)
        pack_w_kernel<<<g, 256>>>(w);
    }

    static int smem_set = 0;
    if (!smem_set) {
        cudaFuncSetAttribute(bgemm_kernel, cudaFuncAttributeMaxDynamicSharedMemorySize,
                             GEMM_SMEM);
        smem_set = 1;
    }
    dim3 grid(B_ROWS / BM, C_PAD / BN);      // (64, 8)
    bgemm_kernel<<<grid, 256, GEMM_SMEM>>>(out);
}